// round 9
// baseline (speedup 1.0000x reference)
#include <cuda_runtime.h>
#include <cstdint>

#define MARGIN 0.1f
#define WR 4                            // rows per stage (per warp)
#define STG_FLOATS (WR * 128)           // 512
#define STG_BYTES  (STG_FLOATS * 4)     // 2048
#define LAB_BYTES  (WR * 4)             // 16
#define NS 2                            // stages per warp
#define NWARPS_CTA 8
#define NUM_BLOCKS 512                  // 4096 warps: 65536/4096 = 16 exact

// Persistent device scratch; reset by last block each call so graph replays
// are deterministic.
__device__ double       g_total = 0.0;
__device__ unsigned int g_count = 0u;

__device__ __forceinline__ uint32_t smem_u32(const void* p) {
    return (uint32_t)__cvta_generic_to_shared(p);
}
__device__ __forceinline__ void mbar_init(uint32_t a, uint32_t cnt) {
    asm volatile("mbarrier.init.shared.b64 [%0], %1;" :: "r"(a), "r"(cnt) : "memory");
}
__device__ __forceinline__ void mbar_expect_tx(uint32_t a, uint32_t bytes) {
    asm volatile("mbarrier.arrive.expect_tx.shared.b64 _, [%0], %1;"
                 :: "r"(a), "r"(bytes) : "memory");
}
__device__ __forceinline__ void bulk_g2s(uint32_t dst, const void* src,
                                         uint32_t bytes, uint32_t mbar) {
    asm volatile(
        "cp.async.bulk.shared::cluster.global.mbarrier::complete_tx::bytes "
        "[%0], [%1], %2, [%3];"
        :: "r"(dst), "l"(src), "r"(bytes), "r"(mbar) : "memory");
}
__device__ __forceinline__ void mbar_wait(uint32_t a, uint32_t parity) {
    asm volatile(
        "{\n\t"
        ".reg .pred P;\n\t"
        "WAIT_%=:\n\t"
        "mbarrier.try_wait.parity.acquire.cta.shared::cta.b64 P, [%0], %1, 0x989680;\n\t"
        "@P bra.uni DONE_%=;\n\t"
        "bra.uni WAIT_%=;\n\t"
        "DONE_%=:\n\t"
        "}"
        :: "r"(a), "r"(parity) : "memory");
}
__device__ __forceinline__ void fence_async() {
    asm volatile("fence.proxy.async.shared::cta;" ::: "memory");
}

__global__ void __launch_bounds__(256)
margin_loss_kernel(const float* __restrict__ x,
                   const int* __restrict__ labels,   // int32 (JAX x64 disabled)
                   float* __restrict__ out,
                   int N)
{
    // Per-warp private pipelines: no block barriers in the main loop.
    __shared__ __align__(128) float sdata[NWARPS_CTA][NS][STG_FLOATS]; // 32 KB
    __shared__ __align__(16)  int   slab[NWARPS_CTA][NS][WR];
    __shared__ __align__(8)   unsigned long long smbar[NWARPS_CTA][NS];
    __shared__ float warp_sums[NWARPS_CTA];
    __shared__ bool  is_last;

    const int tid  = threadIdx.x;
    const int warp = tid >> 5;
    const int lane = tid & 31;

    if (lane == 0) {
        #pragma unroll
        for (int s = 0; s < NS; s++) mbar_init(smem_u32(&smbar[warp][s]), 1);
    }
    fence_async();
    __syncthreads();     // all mbarriers visible before any TMA

    // Balanced contiguous partition of 4-row batches across all warps.
    const int nb     = N / WR;                               // 65536
    const int gwarps = (NUM_BLOCKS * 256) >> 5;              // 4096
    const int wgid   = blockIdx.x * NWARPS_CTA + warp;
    const int qcnt   = nb / gwarps;
    const int rem    = nb % gwarps;
    const int cnt    = qcnt + (wgid < rem);
    const int start  = wgid * qcnt + min(wgid, rem);

    // Issue TMA fill of stage s with batch (start + t). Lane 0 only.
    auto fill = [&](int s, int t) {
        const uint32_t mb = smem_u32(&smbar[warp][s]);
        mbar_expect_tx(mb, STG_BYTES + LAB_BYTES);
        bulk_g2s(smem_u32(&sdata[warp][s][0]),
                 x + (size_t)(start + t) * STG_FLOATS, STG_BYTES, mb);
        bulk_g2s(smem_u32(&slab[warp][s][0]),
                 labels + (size_t)(start + t) * WR, LAB_BYTES, mb);
    };

    float wsum = 0.0f;

    if (cnt > 0) {
        if (lane == 0) {
            fill(0, 0);
            if (cnt > 1) fill(1, 1);
        }

        for (int i = 0; i < cnt; i++) {
            const int s = i & (NS - 1);
            mbar_wait(smem_u32(&smbar[warp][s]), (i >> 1) & 1);

            const float* xs = sdata[warp][s];
            #pragma unroll
            for (int r = 0; r < WR; r++) {
                const int lb  = slab[warp][s][r];
                const float c = xs[r * 128 + lb];                 // smem bcast
                const float4 v = reinterpret_cast<const float4*>(xs + r * 128)[lane];
                const float m = MARGIN - c;
                wsum += fmaxf(m + v.x, 0.0f);
                wsum += fmaxf(m + v.y, 0.0f);
                wsum += fmaxf(m + v.z, 0.0f);
                wsum += fmaxf(m + v.w, 0.0f);
            }

            __syncwarp();                 // warp done reading stage s
            if (lane == 0 && i + NS < cnt) {
                fence_async();            // order generic reads before overwrite
                fill(s, i + NS);
            }
        }
    }

    // Warp reduction; remove the j==label MARGIN term per processed row.
    #pragma unroll
    for (int o = 16; o > 0; o >>= 1)
        wsum += __shfl_down_sync(0xffffffffu, wsum, o);
    if (lane == 0) wsum -= MARGIN * (float)(cnt * WR);

    if (lane == 0) warp_sums[warp] = wsum;
    __syncthreads();

    if (tid == 0) {
        double bsum = 0.0;
        #pragma unroll
        for (int wi = 0; wi < NWARPS_CTA; wi++) bsum += (double)warp_sums[wi];
        atomicAdd(&g_total, bsum);
        __threadfence();
        unsigned int t = atomicAdd(&g_count, 1u);
        is_last = (t == gridDim.x - 1);
    }
    __syncthreads();

    if (is_last && tid == 0) {
        const double total = g_total;
        // mean over N * (G-1) pairs, G = 128
        out[0] = (float)(total / ((double)N * 127.0));
        g_total = 0.0;
        g_count = 0u;
    }
}

extern "C" void kernel_launch(void* const* d_in, const int* in_sizes, int n_in,
                              void* d_out, int out_size)
{
    const float* x      = (const float*)d_in[0];
    const int*   labels = (const int*)d_in[1];
    float*       out    = (float*)d_out;

    const int N = in_sizes[1];                  // labels count = rows

    margin_loss_kernel<<<NUM_BLOCKS, 256>>>(x, labels, out, N);
}

// round 10
// speedup vs baseline: 1.4266x; 1.4266x over previous
#include <cuda_runtime.h>
#include <cstdint>

#define MARGIN 0.1f
#define RPT 16                          // rows per tile/stage
#define TILE_FLOATS (RPT * 128)         // 2048
#define TILE_BYTES  (TILE_FLOATS * 4)   // 8192
#define LAB_BYTES   (RPT * 4)           // 64
#define NS 4                            // pipeline stages
#define NCW 8                           // consumer warps
#define NTHREADS 288                    // 8 consumer warps + 1 producer warp
#define NUM_BLOCKS 888                  // 148 SMs * 6

// Persistent device scratch; reset by last block each call so graph replays
// are deterministic.
__device__ double       g_total = 0.0;
__device__ unsigned int g_count = 0u;

__device__ __forceinline__ uint32_t smem_u32(const void* p) {
    return (uint32_t)__cvta_generic_to_shared(p);
}
__device__ __forceinline__ void mbar_init(uint32_t a, uint32_t cnt) {
    asm volatile("mbarrier.init.shared.b64 [%0], %1;" :: "r"(a), "r"(cnt) : "memory");
}
__device__ __forceinline__ void mbar_expect_tx(uint32_t a, uint32_t bytes) {
    asm volatile("mbarrier.arrive.expect_tx.shared.b64 _, [%0], %1;"
                 :: "r"(a), "r"(bytes) : "memory");
}
__device__ __forceinline__ void mbar_arrive(uint32_t a) {
    asm volatile("mbarrier.arrive.shared.b64 _, [%0];" :: "r"(a) : "memory");
}
__device__ __forceinline__ void bulk_g2s(uint32_t dst, const void* src,
                                         uint32_t bytes, uint32_t mbar) {
    asm volatile(
        "cp.async.bulk.shared::cluster.global.mbarrier::complete_tx::bytes "
        "[%0], [%1], %2, [%3];"
        :: "r"(dst), "l"(src), "r"(bytes), "r"(mbar) : "memory");
}
__device__ __forceinline__ void mbar_wait(uint32_t a, uint32_t parity) {
    asm volatile(
        "{\n\t"
        ".reg .pred P;\n\t"
        "WAIT_%=:\n\t"
        "mbarrier.try_wait.parity.acquire.cta.shared::cta.b64 P, [%0], %1, 0x989680;\n\t"
        "@P bra.uni DONE_%=;\n\t"
        "bra.uni WAIT_%=;\n\t"
        "DONE_%=:\n\t"
        "}"
        :: "r"(a), "r"(parity) : "memory");
}
__device__ __forceinline__ void fence_async() {
    asm volatile("fence.proxy.async.shared::cta;" ::: "memory");
}

__global__ void __launch_bounds__(NTHREADS)
margin_loss_kernel(const float* __restrict__ x,
                   const int* __restrict__ labels,   // int32 (JAX x64 disabled)
                   float* __restrict__ out,
                   int N)
{
    __shared__ __align__(128) float sdata[NS][TILE_FLOATS];   // 32 KB
    __shared__ __align__(16)  int   slab[NS][RPT];
    __shared__ __align__(8)   unsigned long long full_mb[NS], empty_mb[NS];
    __shared__ float warp_sums[NCW];
    __shared__ bool  is_last;

    const int tid  = threadIdx.x;
    const int warp = tid >> 5;
    const int lane = tid & 31;
    const int ntiles = N / RPT;                        // 16384

    if (tid == 0) {
        #pragma unroll
        for (int s = 0; s < NS; s++) {
            mbar_init(smem_u32(&full_mb[s]), 1);       // tx-based completion
            mbar_init(smem_u32(&empty_mb[s]), NCW);    // 8 consumer arrivals
        }
        fence_async();
    }
    __syncthreads();

    // How many tiles this CTA handles (grid-stride).
    int cnt = 0;
    for (int j = blockIdx.x; j < ntiles; j += gridDim.x) cnt++;

    if (warp == NCW) {
        // ── Producer warp: lane 0 issues TMA fills, running up to NS ahead ──
        if (lane == 0) {
            int j = blockIdx.x;
            for (int i = 0; i < cnt; i++, j += gridDim.x) {
                const int s = i & (NS - 1);
                const int k = i >> 2;                      // use-index of stage s
                // First NS fills pass immediately (parity 1 = pre-initial phase);
                // afterwards wait for consumers to drain the stage.
                mbar_wait(smem_u32(&empty_mb[s]), (k & 1) ^ 1);
                fence_async();
                const uint32_t mb = smem_u32(&full_mb[s]);
                mbar_expect_tx(mb, TILE_BYTES + LAB_BYTES);
                bulk_g2s(smem_u32(&sdata[s][0]),
                         x + (size_t)j * TILE_FLOATS, TILE_BYTES, mb);
                bulk_g2s(smem_u32(&slab[s][0]),
                         labels + (size_t)j * RPT, LAB_BYTES, mb);
            }
        }
    } else {
        // ── Consumer warps: 2 rows per warp per tile ──
        float wsum = 0.0f;
        for (int i = 0; i < cnt; i++) {
            const int s = i & (NS - 1);
            const int k = i >> 2;
            mbar_wait(smem_u32(&full_mb[s]), k & 1);

            const float* xs = sdata[s];
            #pragma unroll
            for (int r0 = 0; r0 < 2; r0++) {
                const int r   = warp * 2 + r0;
                const int lb  = slab[s][r];                // smem bcast
                const float c = xs[r * 128 + lb];          // smem bcast
                const float4 v = reinterpret_cast<const float4*>(xs + r * 128)[lane];
                const float m = MARGIN - c;
                wsum += fmaxf(m + v.x, 0.0f);
                wsum += fmaxf(m + v.y, 0.0f);
                wsum += fmaxf(m + v.z, 0.0f);
                wsum += fmaxf(m + v.w, 0.0f);
            }
            __syncwarp();
            if (lane == 0) mbar_arrive(smem_u32(&empty_mb[s]));
        }

        // Warp reduction; each processed row's j==label term added MARGIN.
        #pragma unroll
        for (int o = 16; o > 0; o >>= 1)
            wsum += __shfl_down_sync(0xffffffffu, wsum, o);
        if (lane == 0) warp_sums[warp] = wsum - MARGIN * (float)(cnt * 2);
    }

    __syncthreads();

    if (tid == 0) {
        double bsum = 0.0;
        #pragma unroll
        for (int wi = 0; wi < NCW; wi++) bsum += (double)warp_sums[wi];
        atomicAdd(&g_total, bsum);
        __threadfence();
        unsigned int t = atomicAdd(&g_count, 1u);
        is_last = (t == gridDim.x - 1);
    }
    __syncthreads();

    if (is_last && tid == 0) {
        const double total = g_total;
        // mean over N * (G-1) pairs, G = 128
        out[0] = (float)(total / ((double)N * 127.0));
        g_total = 0.0;
        g_count = 0u;
    }
}

extern "C" void kernel_launch(void* const* d_in, const int* in_sizes, int n_in,
                              void* d_out, int out_size)
{
    const float* x      = (const float*)d_in[0];
    const int*   labels = (const int*)d_in[1];
    float*       out    = (float*)d_out;

    const int N = in_sizes[1];                  // labels count = rows

    margin_loss_kernel<<<NUM_BLOCKS, NTHREADS>>>(x, labels, out, N);
}

// round 11
// speedup vs baseline: 1.5478x; 1.0850x over previous
#include <cuda_runtime.h>

#define MARGIN 0.1f
#define RPB 4                   // rows per batch (one int4 of labels)
#define NUM_BLOCKS 592          // 148 SMs * 4 CTAs -> single wave, SM-balanced

// Persistent device scratch (no allocations allowed). Reset by the last block
// each call, so every graph replay sees the same initial state.
__device__ double       g_total = 0.0;
__device__ unsigned int g_count = 0u;

__global__ void __launch_bounds__(256, 4)
margin_loss_kernel(const float* __restrict__ x,
                   const int* __restrict__ labels,   // int32 (JAX x64 disabled)
                   float* __restrict__ out,
                   int N)
{
    // Per-warp staging for the correct-class pick: lanes already hold the row,
    // so c comes from smem broadcast instead of a gmem gather.
    __shared__ __align__(16) float sbuf[8][2][RPB * 128];   // 32 KB / CTA

    const int lane     = threadIdx.x & 31;
    const int warp     = threadIdx.x >> 5;
    const int warp_gid = (blockIdx.x * blockDim.x + threadIdx.x) >> 5;
    const int nwarps   = (NUM_BLOCKS * 256) >> 5;      // 4736
    const int nbatch   = N / RPB;

    const float4* x4   = reinterpret_cast<const float4*>(x);
    const int4*   lab4 = reinterpret_cast<const int4*>(labels);

    float wsum  = 0.0f;     // per-thread hinge accumulator
    int   nrows = 0;        // rows this warp processed (for the -MARGIN fixup)

    float4 vA[RPB], vB[RPB];
    int4   lA, lB;

    auto loadv = [&](int bb, float4* vv) {
        const size_t base = (size_t)bb * RPB;
        #pragma unroll
        for (int k = 0; k < RPB; k++)
            vv[k] = __ldcs(&x4[(base + k) * 32 + lane]);   // streaming
    };

    auto compute = [&](int phase, const float4* vv, const int4& L) {
        float* sw = sbuf[warp][phase];
        // Stage the 4 rows (conflict-free float4 stores).
        #pragma unroll
        for (int r = 0; r < RPB; r++)
            reinterpret_cast<float4*>(sw + r * 128)[lane] = vv[r];
        __syncwarp();
        // Correct-class scores: uniform-address smem broadcasts.
        const float m0 = MARGIN - sw[          L.x];
        const float m1 = MARGIN - sw[128     + L.y];
        const float m2 = MARGIN - sw[256     + L.z];
        const float m3 = MARGIN - sw[384     + L.w];

        wsum += fmaxf(m0 + vv[0].x, 0.0f) + fmaxf(m0 + vv[0].y, 0.0f)
              + fmaxf(m0 + vv[0].z, 0.0f) + fmaxf(m0 + vv[0].w, 0.0f);
        wsum += fmaxf(m1 + vv[1].x, 0.0f) + fmaxf(m1 + vv[1].y, 0.0f)
              + fmaxf(m1 + vv[1].z, 0.0f) + fmaxf(m1 + vv[1].w, 0.0f);
        wsum += fmaxf(m2 + vv[2].x, 0.0f) + fmaxf(m2 + vv[2].y, 0.0f)
              + fmaxf(m2 + vv[2].z, 0.0f) + fmaxf(m2 + vv[2].w, 0.0f);
        wsum += fmaxf(m3 + vv[3].x, 0.0f) + fmaxf(m3 + vv[3].y, 0.0f)
              + fmaxf(m3 + vv[3].z, 0.0f) + fmaxf(m3 + vv[3].w, 0.0f);
        nrows += RPB;
    };

    int b = warp_gid;
    if (b < nbatch) {
        lA = __ldg(&lab4[b]);
        loadv(b, vA);
        // Ping-pong pipeline: prefetch next batch while computing current.
        for (;;) {
            const int b1 = b + nwarps;
            if (b1 < nbatch) { lB = __ldg(&lab4[b1]); loadv(b1, vB); }
            compute(0, vA, lA);
            if (b1 >= nbatch) break;

            const int b2 = b1 + nwarps;
            if (b2 < nbatch) { lA = __ldg(&lab4[b2]); loadv(b2, vA); }
            compute(1, vB, lB);
            if (b2 >= nbatch) break;
            b = b2;
        }
    }

    // One warp reduction for everything this warp processed.
    #pragma unroll
    for (int o = 16; o > 0; o >>= 1)
        wsum += __shfl_down_sync(0xffffffffu, wsum, o);
    // Each processed row's j==label term contributed exactly MARGIN; remove.
    if (lane == 0) wsum -= MARGIN * (float)nrows;

    __shared__ float warp_sums[8];
    __shared__ bool  is_last;

    if (lane == 0) warp_sums[warp] = wsum;
    __syncthreads();

    if (threadIdx.x == 0) {
        double bsum = 0.0;
        #pragma unroll
        for (int wi = 0; wi < 8; wi++) bsum += (double)warp_sums[wi];
        atomicAdd(&g_total, bsum);
        __threadfence();
        unsigned int t = atomicAdd(&g_count, 1u);
        is_last = (t == gridDim.x - 1);
    }
    __syncthreads();

    if (is_last && threadIdx.x == 0) {
        const double total = g_total;
        // mean over N * (G-1) pairs, G = 128
        out[0] = (float)(total / ((double)N * 127.0));
        // Reset for the next (graph-replayed) call.
        g_total = 0.0;
        g_count = 0u;
    }
}

extern "C" void kernel_launch(void* const* d_in, const int* in_sizes, int n_in,
                              void* d_out, int out_size)
{
    const float* x      = (const float*)d_in[0];
    const int*   labels = (const int*)d_in[1];
    float*       out    = (float*)d_out;

    const int N = in_sizes[1];                  // labels count = rows

    margin_loss_kernel<<<NUM_BLOCKS, 256>>>(x, labels, out, N);
}

// round 12
// speedup vs baseline: 2.1850x; 1.4117x over previous
#include <cuda_runtime.h>
#include <cstdint>

#define MARGIN 0.1f
#define RPT 32                          // rows per TMA tile
#define TILE_FLOATS (RPT * 128)         // 4096
#define TILE_BYTES  (TILE_FLOATS * 4)   // 16384
#define LAB_BYTES   (RPT * 4)           // 128
#define RPB 4                           // rows per LDG batch
#define NUM_BLOCKS 592                  // 148 SMs * 4 CTAs

// Persistent device scratch; reset by last block each call (graph-replay safe).
__device__ double       g_total = 0.0;
__device__ unsigned int g_count = 0u;

__device__ __forceinline__ uint32_t smem_u32(const void* p) {
    return (uint32_t)__cvta_generic_to_shared(p);
}
__device__ __forceinline__ void mbar_init(uint32_t a, uint32_t cnt) {
    asm volatile("mbarrier.init.shared.b64 [%0], %1;" :: "r"(a), "r"(cnt) : "memory");
}
__device__ __forceinline__ void mbar_expect_tx(uint32_t a, uint32_t bytes) {
    asm volatile("mbarrier.arrive.expect_tx.shared.b64 _, [%0], %1;"
                 :: "r"(a), "r"(bytes) : "memory");
}
__device__ __forceinline__ void bulk_g2s(uint32_t dst, const void* src,
                                         uint32_t bytes, uint32_t mbar) {
    asm volatile(
        "cp.async.bulk.shared::cluster.global.mbarrier::complete_tx::bytes "
        "[%0], [%1], %2, [%3];"
        :: "r"(dst), "l"(src), "r"(bytes), "r"(mbar) : "memory");
}
__device__ __forceinline__ void mbar_wait(uint32_t a, uint32_t parity) {
    asm volatile(
        "{\n\t"
        ".reg .pred P;\n\t"
        "WAIT_%=:\n\t"
        "mbarrier.try_wait.parity.acquire.cta.shared::cta.b64 P, [%0], %1, 0x989680;\n\t"
        "@P bra.uni DONE_%=;\n\t"
        "bra.uni WAIT_%=;\n\t"
        "DONE_%=:\n\t"
        "}"
        :: "r"(a), "r"(parity) : "memory");
}
__device__ __forceinline__ void fence_async() {
    asm volatile("fence.proxy.async.shared::cta;" ::: "memory");
}

__global__ void __launch_bounds__(256, 4)
margin_loss_kernel(const float* __restrict__ x,
                   const int* __restrict__ labels,   // int32 (JAX x64 disabled)
                   float* __restrict__ out,
                   int N)
{
    __shared__ __align__(128) float sdata[2][TILE_FLOATS];   // 32 KB
    __shared__ __align__(16)  int   slab[2][RPT];
    __shared__ __align__(8)   unsigned long long smbar[2];
    __shared__ float warp_sums[8];
    __shared__ bool  is_last;

    const int tid  = threadIdx.x;
    const int warp = tid >> 5;
    const int lane = tid & 31;

    const int halfRows = N >> 1;
    const int ntT   = halfRows / RPT;                 // TMA tiles   (4096)
    const int nbL   = halfRows / RPB;                 // LDG batches (32768)
    const int nwarps = (NUM_BLOCKS * 256) >> 5;       // 4736
    const int wgid   = blockIdx.x * 8 + warp;

    const int cntT = (blockIdx.x < ntT) ? (ntT - 1 - blockIdx.x) / gridDim.x + 1 : 0;
    const int cntL = (wgid       < nbL) ? (nbL - 1 - wgid)       / nwarps     + 1 : 0;

    const float4* x4   = reinterpret_cast<const float4*>(x);
    const int4*   lab4 = reinterpret_cast<const int4*>(labels);

    if (tid == 0) {
        mbar_init(smem_u32(&smbar[0]), 1);
        mbar_init(smem_u32(&smbar[1]), 1);
        fence_async();
    }
    __syncthreads();

    // TMA prologue: fill both stages.
    if (tid == 0) {
        #pragma unroll
        for (int s = 0; s < 2; s++) {
            if (s < cntT) {
                const int t = blockIdx.x + s * gridDim.x;
                const uint32_t mb = smem_u32(&smbar[s]);
                mbar_expect_tx(mb, TILE_BYTES + LAB_BYTES);
                bulk_g2s(smem_u32(&sdata[s][0]), x + (size_t)t * TILE_FLOATS,
                         TILE_BYTES, mb);
                bulk_g2s(smem_u32(&slab[s][0]),  labels + (size_t)t * RPT,
                         LAB_BYTES, mb);
            }
        }
    }

    float wsum  = 0.0f;
    int   nrows = 0;

    // ── LDG stream state (rows [halfRows, N)) ──
    float4 vA[RPB], vB[RPB];
    float  cA[RPB], cB[RPB];

    auto prefetchL = [&](int k, float4* vv, float* cc) {
        const int bb = wgid + k * nwarps;
        const size_t rbase = (size_t)halfRows + (size_t)bb * RPB;
        const int4 L = __ldg(&lab4[(halfRows >> 2) + bb]);
        cc[0] = __ldg(&x[(rbase + 0) * 128 + L.x]);
        cc[1] = __ldg(&x[(rbase + 1) * 128 + L.y]);
        cc[2] = __ldg(&x[(rbase + 2) * 128 + L.z]);
        cc[3] = __ldg(&x[(rbase + 3) * 128 + L.w]);
        #pragma unroll
        for (int j = 0; j < RPB; j++)
            vv[j] = __ldcs(&x4[(rbase + j) * 32 + lane]);
    };
    auto computeL = [&](const float4* vv, const float* cc) {
        #pragma unroll
        for (int j = 0; j < RPB; j++) {
            const float m = MARGIN - cc[j];
            wsum += fmaxf(m + vv[j].x, 0.0f) + fmaxf(m + vv[j].y, 0.0f)
                  + fmaxf(m + vv[j].z, 0.0f) + fmaxf(m + vv[j].w, 0.0f);
        }
        nrows += RPB;
    };

    if (cntL > 0) prefetchL(0, vA, cA);

    // ── Main loop: one TMA tile + one LDG batch per iteration ──
    for (int k = 0; k < cntT; k++) {
        // Prefetch next LDG batch (other buffer).
        if (k + 1 < cntL) {
            if (k & 1) prefetchL(k + 1, vA, cA);
            else       prefetchL(k + 1, vB, cB);
        }

        // TMA tile: 4 smem rows per warp.
        const int s = k & 1;
        mbar_wait(smem_u32(&smbar[s]), (k >> 1) & 1);
        {
            const float* xs = sdata[s];
            #pragma unroll
            for (int rr = 0; rr < 4; rr++) {
                const int r   = warp * 4 + rr;
                const int lb  = slab[s][r];
                const float c = xs[r * 128 + lb];               // smem bcast
                const float4 v = reinterpret_cast<const float4*>(xs + r * 128)[lane];
                const float m = MARGIN - c;
                wsum += fmaxf(m + v.x, 0.0f) + fmaxf(m + v.y, 0.0f)
                      + fmaxf(m + v.z, 0.0f) + fmaxf(m + v.w, 0.0f);
            }
            nrows += 4;
        }

        // Current LDG batch.
        if (k < cntL) {
            if (k & 1) computeL(vB, cB);
            else       computeL(vA, cA);
        }

        __syncthreads();              // tile fully consumed
        if (tid == 0 && k + 2 < cntT) {
            const int t = blockIdx.x + (size_t)(k + 2) * gridDim.x;
            fence_async();
            const uint32_t mb = smem_u32(&smbar[s]);
            mbar_expect_tx(mb, TILE_BYTES + LAB_BYTES);
            bulk_g2s(smem_u32(&sdata[s][0]), x + (size_t)t * TILE_FLOATS,
                     TILE_BYTES, mb);
            bulk_g2s(smem_u32(&slab[s][0]),  labels + (size_t)t * RPT,
                     LAB_BYTES, mb);
        }
    }

    // Drain leftover LDG batches (no barriers needed).
    for (int k = cntT; k < cntL; k++) {
        if (k + 1 < cntL) {
            if (k & 1) prefetchL(k + 1, vA, cA);
            else       prefetchL(k + 1, vB, cB);
        }
        if (k & 1) computeL(vB, cB);
        else       computeL(vA, cA);
    }

    // Warp reduction; remove the j==label MARGIN term per processed row.
    #pragma unroll
    for (int o = 16; o > 0; o >>= 1)
        wsum += __shfl_down_sync(0xffffffffu, wsum, o);
    if (lane == 0) warp_sums[warp] = wsum - MARGIN * (float)nrows;

    __syncthreads();

    if (tid == 0) {
        double bsum = 0.0;
        #pragma unroll
        for (int wi = 0; wi < 8; wi++) bsum += (double)warp_sums[wi];
        atomicAdd(&g_total, bsum);
        __threadfence();
        unsigned int t = atomicAdd(&g_count, 1u);
        is_last = (t == gridDim.x - 1);
    }
    __syncthreads();

    if (is_last && tid == 0) {
        const double total = g_total;
        // mean over N * (G-1) pairs, G = 128
        out[0] = (float)(total / ((double)N * 127.0));
        g_total = 0.0;
        g_count = 0u;
    }
}

extern "C" void kernel_launch(void* const* d_in, const int* in_sizes, int n_in,
                              void* d_out, int out_size)
{
    const float* x      = (const float*)d_in[0];
    const int*   labels = (const int*)d_in[1];
    float*       out    = (float*)d_out;

    const int N = in_sizes[1];                  // labels count = rows

    margin_loss_kernel<<<NUM_BLOCKS, 256>>>(x, labels, out, N);
}